// round 17
// baseline (speedup 1.0000x reference)
#include <cuda_runtime.h>
#include <cuda_fp16.h>
#include <cstdint>

// Soft decision tree forward via mma.sync fp16/fp16-acc (family-common sm_103;
// tcgen05 unavailable in this toolchain path).
// Chain nodes (2^k)-1, k=0..5 -> N = 6*64 = 384.
// GEMM H = X[65536 x 128] @ W1cat[128 x 384], fp16 x fp16 -> fp16 accumulate
// (k=16 dots are full precision inside the MMA; 8 inter-MMA roundings).
// Epilogue fp32: relu -> dot W2 -> sigmoid -> 6-level leaf fold.
// R14 = R13 (persistent 128 CTAs x 4 M=128 tiles, W staged once, X prefetch,
// fp16 acc) + R11's 512-thread/16-warp layout (warp tile 64x48, atomicAdd
// rowsum merge). fp16 acc -> 48 acc regs/thread -> no spill at 128-reg cap.

#define THREADS 512      // 16 warps: wm = wid&1 (M half), ws = wid>>1 (N strip)
#define M_CTA   128
#define KDIM    128
#define NTOT    384
#define NCTAS   128
#define TILES   4
#define XPITCH  288      // bytes/row (72 words): conflict-free lds64
#define WPITCH  288

// W1 (live nodes) fp16, [n=384][k=128], k permuted within 16-blocks so that
// pairs (2t4,2t4+1) and (2t4+8,2t4+9) are adjacent -> frags = one LDS.64.
__device__ __align__(16) __half g_Wh[NTOT * KDIM];

// ---- smem layout (bytes) ----
#define OFF_B1    0
#define OFF_W2    1536
#define OFF_B2    3072
#define OFF_LEAF  3104
#define OFF_RS    3360                 // rowsum 6*132*4 = 3168 -> 6528
#define OFF_XC    6656                 // converted X: 128 * 288 = 36864
#define OFF_W     43520                // W: 384 * 288 = 110592
#define OFF_XR    154112               // raw X: 128 rows * 512B = 65536
#define SMEM_BYTES 219648              // ~214.5 KB, 1 CTA/SM

// ---------------- helpers ----------------
__device__ __forceinline__ uint32_t smem_u32_of(const void* p) {
    uint32_t a;
    asm("{ .reg .u64 t; cvta.to.shared.u64 t, %1; cvt.u32.u64 %0, t; }"
        : "=r"(a) : "l"(p));
    return a;
}
__device__ __forceinline__ void cp_async16(uint32_t dst, const void* src) {
    asm volatile("cp.async.cg.shared.global [%0], [%1], 16;" :: "r"(dst), "l"(src));
}
__device__ __forceinline__ void lds64(uint32_t& a, uint32_t& b, uint32_t addr) {
    asm volatile("ld.shared.v2.u32 {%0,%1}, [%2];" : "=r"(a), "=r"(b) : "r"(addr));
}
__device__ __forceinline__ void lds128f(float4& v, uint32_t addr) {
    asm volatile("ld.shared.v4.f32 {%0,%1,%2,%3}, [%4];"
                 : "=f"(v.x), "=f"(v.y), "=f"(v.z), "=f"(v.w) : "r"(addr));
}
__device__ __forceinline__ void sts32(uint32_t addr, uint32_t v) {
    asm volatile("st.shared.u32 [%0], %1;" :: "r"(addr), "r"(v));
}
// m16n8k16, all-fp16 (D/C fp16): 2-reg accumulator
__device__ __forceinline__ void mma_f16acc(uint32_t* c, const uint32_t* a,
                                           uint32_t b0, uint32_t b1) {
    asm volatile(
        "mma.sync.aligned.m16n8k16.row.col.f16.f16.f16.f16 "
        "{%0,%1}, {%2,%3,%4,%5}, {%6,%7}, {%0,%1};"
        : "+r"(c[0]), "+r"(c[1])
        : "r"(a[0]), "r"(a[1]), "r"(a[2]), "r"(a[3]), "r"(b0), "r"(b1));
}

// ---------------- pre-kernel: W1 -> fp16, permuted k ----------------
__global__ void convert_w1_kernel(const float* __restrict__ W1) {
    int idx = blockIdx.x * blockDim.x + threadIdx.x;
    if (idx >= NTOT * KDIM) return;
    int k = idx & 127;
    int n = idx >> 7;
    int node = n >> 6, h = n & 63;
    int gnode = (1 << node) - 1;            // 0,1,3,7,15,31
    float v = W1[(size_t)gnode * (KDIM * 64) + (size_t)k * 64 + h];
    int blk = k >> 4, kk = k & 15, q = kk >> 1;
    int pos = (q & 3) * 2 + (q >> 2);
    g_Wh[n * KDIM + blk * 16 + pos * 2 + (kk & 1)] = __float2half_rn(v);
}

// ---------------- main kernel ----------------
__global__ __launch_bounds__(THREADS, 1)
void sdt_fp16_kernel(const float* __restrict__ x,
                     const float* __restrict__ b1,
                     const float* __restrict__ W2,
                     const float* __restrict__ b2,
                     const float* __restrict__ leaf,
                     float* __restrict__ out)
{
    extern __shared__ char smem[];
    const uint32_t sbase = smem_u32_of(smem);
    float* b1sh   = (float*)(smem + OFF_B1);
    float* W2s    = (float*)(smem + OFF_W2);
    float* b2s    = (float*)(smem + OFF_B2);
    float* leafs  = (float*)(smem + OFF_LEAF);
    float* rowsum = (float*)(smem + OFF_RS);

    const int tid  = threadIdx.x;
    const int lane = tid & 31;
    const int wid  = tid >> 5;
    const int wm   = wid & 1;               // M half (64 rows)
    const int ws   = wid >> 1;              // N strip (48 cols), 0..7
    const int g    = lane >> 2;
    const int t4   = lane & 3;
    const int bx   = blockIdx.x;

    // ---- prologue: stage W (once) + raw X tile 0, linear addressing ----
    {
        uint32_t wdst = sbase + OFF_W + (uint32_t)((tid >> 4) * WPITCH + (tid & 15) * 16);
        const __half* wsrc = g_Wh + tid * 8;
        #pragma unroll
        for (int it = 0; it < 12; it++) {   // 6144 / 512
            cp_async16(wdst, wsrc);
            wdst += 32 * WPITCH;            // 512 idx = 32 rows
            wsrc += 512 * 8;
        }
    }
    {
        const float* xsrc = x + (size_t)bx * TILES * M_CTA * KDIM + tid * 4;
        uint32_t xdst = sbase + OFF_XR + (uint32_t)tid * 16;
        #pragma unroll
        for (int it = 0; it < 8; it++) {    // 4096 / 512
            cp_async16(xdst, xsrc);
            xsrc += 512 * 4;
            xdst += 8192;
        }
    }
    asm volatile("cp.async.commit_group;" ::: "memory");

    // small tensors for the 6 live nodes
    for (int i = tid; i < NTOT; i += THREADS) {
        int node = i >> 6, h = i & 63;
        int gl = ((1 << node) - 1) * 64 + h;
        b1sh[i] = b1[gl];
        W2s[i]  = W2[gl];
    }
    if (tid < 6)  b2s[tid]   = b2[(1 << tid) - 1];
    if (tid < 64) leafs[tid] = leaf[tid];

    asm volatile("cp.async.wait_group 0;" ::: "memory");
    __syncthreads();

    // hoisted convert addressing (iteration-invariant parts)
    const int c4i = tid & 31, mI = c4i & 3;
    const uint32_t cvt_src0 = sbase + OFF_XR + (uint32_t)tid * 16;
    const uint32_t cvt_dst0 = sbase + OFF_XC
        + (uint32_t)((tid >> 5) * XPITCH + (c4i >> 2) * 32
                     + ((mI & 1) * 4 + (mI >> 1)) * 4);

    const uint32_t xb = sbase + OFF_XC + (uint32_t)((wm * 64 + g) * XPITCH + t4 * 8);
    const uint32_t wb = sbase + OFF_W  + (uint32_t)((ws * 48 + g) * WPITCH + t4 * 8);
    const int c0    = ws * 48;              // strip base column
    const int nodeA = c0 >> 6;
    const int two   = (((c0 + 40) >> 6) != nodeA);

    for (int ti = 0; ti < TILES; ti++) {
        const int rowbase = (bx * TILES + ti) * M_CTA;

        // ---- convert raw X -> fp16 interleaved Xcvt; zero rowsum ----
        {
            uint32_t s = cvt_src0, d = cvt_dst0;
            #pragma unroll
            for (int it = 0; it < 8; it++) {
                float4 v;
                lds128f(v, s);
                __half2 h01 = __floats2half2_rn(v.x, v.y);
                __half2 h23 = __floats2half2_rn(v.z, v.w);
                sts32(d,     *(uint32_t*)&h01);
                sts32(d + 8, *(uint32_t*)&h23);
                s += 8192;
                d += 4608;                  // 16 rows * 288
            }
        }
        for (int i = tid; i < 6 * 132; i += THREADS) rowsum[i] = 0.0f;
        __syncthreads();

        // ---- prefetch raw X for next tile (overlaps MMA below) ----
        if (ti + 1 < TILES) {
            const float* xsrc = x + (size_t)(bx * TILES + ti + 1) * M_CTA * KDIM + tid * 4;
            uint32_t xdst = sbase + OFF_XR + (uint32_t)tid * 16;
            #pragma unroll
            for (int it = 0; it < 8; it++) {
                cp_async16(xdst, xsrc);
                xsrc += 512 * 4;
                xdst += 8192;
            }
            asm volatile("cp.async.commit_group;" ::: "memory");
        }

        // ---- MMA: 8 k-steps over full k=128; warp tile 64 x 48, fp16 acc ----
        uint32_t acc[4][6][2];
        #pragma unroll
        for (int mt = 0; mt < 4; mt++)
            #pragma unroll
            for (int nt = 0; nt < 6; nt++) {
                acc[mt][nt][0] = 0u;
                acc[mt][nt][1] = 0u;
            }

        #pragma unroll
        for (int ks = 0; ks < 8; ks++) {
            const uint32_t ko = (uint32_t)(ks * 32);
            uint32_t A[4][4];
            #pragma unroll
            for (int mt = 0; mt < 4; mt++) {
                lds64(A[mt][0], A[mt][2], xb + (uint32_t)(mt * 16 * XPITCH) + ko);
                lds64(A[mt][1], A[mt][3], xb + (uint32_t)(mt * 16 * XPITCH) + 8 * XPITCH + ko);
            }
            #pragma unroll
            for (int nt = 0; nt < 6; nt++) {
                uint32_t b0, b1f;
                lds64(b0, b1f, wb + (uint32_t)(nt * 8 * WPITCH) + ko);
                #pragma unroll
                for (int mt = 0; mt < 4; mt++)
                    mma_f16acc(acc[mt][nt], A[mt], b0, b1f);
            }
        }

        // ---- epilogue (fp32): per-node partials, merge via shared atomics ----
        {
            float sA[4][2], sB[4][2];
            #pragma unroll
            for (int mt = 0; mt < 4; mt++) {
                sA[mt][0] = sA[mt][1] = 0.0f;
                sB[mt][0] = sB[mt][1] = 0.0f;
            }
            #pragma unroll
            for (int nt = 0; nt < 6; nt++) {
                int colb = c0 + nt * 8;
                int col  = colb + t4 * 2;
                float ba  = b1sh[col], bb = b1sh[col + 1];
                float w2a = W2s[col],  w2b = W2s[col + 1];
                bool isA  = ((colb >> 6) == nodeA);
                #pragma unroll
                for (int mt = 0; mt < 4; mt++) {
                    float2 f0 = __half22float2(*reinterpret_cast<__half2*>(&acc[mt][nt][0]));
                    float2 f1 = __half22float2(*reinterpret_cast<__half2*>(&acc[mt][nt][1]));
                    float v0 = fmaf(fmaxf(f0.x + ba, 0.0f), w2a,
                                    fmaxf(f0.y + bb, 0.0f) * w2b);
                    float v1 = fmaf(fmaxf(f1.x + ba, 0.0f), w2a,
                                    fmaxf(f1.y + bb, 0.0f) * w2b);
                    if (isA) { sA[mt][0] += v0; sA[mt][1] += v1; }
                    else     { sB[mt][0] += v0; sB[mt][1] += v1; }
                }
            }
            #pragma unroll
            for (int mt = 0; mt < 4; mt++) {
                #pragma unroll
                for (int h = 0; h < 2; h++) {
                    float a = sA[mt][h], b = sB[mt][h];
                    a += __shfl_xor_sync(0xffffffffu, a, 1);
                    a += __shfl_xor_sync(0xffffffffu, a, 2);
                    b += __shfl_xor_sync(0xffffffffu, b, 1);
                    b += __shfl_xor_sync(0xffffffffu, b, 2);
                    if (t4 == 0) {
                        int r = wm * 64 + mt * 16 + g + h * 8;
                        atomicAdd(&rowsum[nodeA * 132 + r], a);
                        if (two) atomicAdd(&rowsum[(nodeA + 1) * 132 + r], b);
                    }
                }
            }
        }
        __syncthreads();

        if (tid < M_CTA) {
            float p[6];
            #pragma unroll
            for (int k = 0; k < 6; k++) {
                float z = rowsum[k * 132 + tid] + b2s[k];
                p[k] = 1.0f / (1.0f + __expf(-z));
            }
            float v[32];
            #pragma unroll
            for (int m = 0; m < 32; m++)
                v[m] = fmaf(p[0], leafs[2 * m + 1], (1.0f - p[0]) * leafs[2 * m]);
            #pragma unroll
            for (int k = 1; k < 6; k++) {
                int len = 32 >> k;
                #pragma unroll
                for (int m = 0; m < 32; m++)
                    if (m < len)
                        v[m] = fmaf(p[k], v[2 * m + 1], (1.0f - p[k]) * v[2 * m]);
            }
            out[rowbase + tid] = v[0];
        }

        if (ti + 1 < TILES)
            asm volatile("cp.async.wait_group 0;" ::: "memory");
        __syncthreads();
    }
}

// ---------------- launch ----------------
extern "C" void kernel_launch(void* const* d_in, const int* in_sizes, int n_in,
                              void* d_out, int out_size)
{
    const float* x    = (const float*)d_in[0];
    const float* W1   = (const float*)d_in[1];
    const float* b1   = (const float*)d_in[2];
    const float* W2   = (const float*)d_in[3];
    const float* b2   = (const float*)d_in[4];
    const float* leaf = (const float*)d_in[5];
    float* out = (float*)d_out;

    cudaFuncSetAttribute(sdt_fp16_kernel, cudaFuncAttributeMaxDynamicSharedMemorySize, SMEM_BYTES);

    convert_w1_kernel<<<(NTOT * KDIM + 255) / 256, 256>>>(W1);
    sdt_fp16_kernel<<<NCTAS, THREADS, SMEM_BYTES>>>(x, b1, W2, b2, leaf, out);
}